// round 16
// baseline (speedup 1.0000x reference)
#include <cuda_runtime.h>
#include <cuda_fp16.h>
#include <cstdint>
#include <cstddef>

// ---------------------------------------------------------------------------
// Problem constants
// ---------------------------------------------------------------------------
#define M_ROWS   8192        // 2*4096
#define N_COLS   11008
#define K_DIM    4096
#define KITERS   128         // K = 4096, BK = 32
#define BM       128
#define BN       256
#define BK       32
#define NSTG     4
#define TILES_M  (M_ROWS / BM)      // 64
#define TILES_N  (N_COLS / BN)      // 43
#define GROUP_M  8

#define A_STG    8192               // 128 rows x 64B
#define B_STG    16384              // 256 rows x 64B
#define STG_BYTES (A_STG + B_STG)   // 24576
#define B_OFF     A_STG
#define SMEM_TOTAL (NSTG * STG_BYTES)   // 98304

// ---------------------------------------------------------------------------
// Device scratch (allocation-free rule: __device__ globals)
// ---------------------------------------------------------------------------
__device__ __align__(256) __half g_A[(size_t)M_ROWS * K_DIM];  // fp16(x_q)
__device__ __align__(256) __half g_B[(size_t)N_COLS * K_DIM];  // fp16(W)

// ---------------------------------------------------------------------------
// Helpers (compute_103-safe vocabulary: cp.async / ldmatrix / mma.sync)
// ---------------------------------------------------------------------------
__device__ __forceinline__ uint32_t smem_u32(const void* p) {
    uint32_t a;
    asm("{ .reg .u64 t; cvta.to.shared.u64 t, %1; cvt.u32.u64 %0, t; }" : "=r"(a) : "l"(p));
    return a;
}

#define CP_ASYNC16(dst, src) \
    asm volatile("cp.async.cg.shared.global [%0], [%1], 16;" :: "r"(dst), "l"(src))
#define CP_COMMIT() asm volatile("cp.async.commit_group;" ::: "memory")
#define CP_WAIT(N)  asm volatile("cp.async.wait_group %0;" :: "n"(N) : "memory")

#define LDSM4(r, a) \
    asm volatile("ldmatrix.sync.aligned.m8n8.x4.shared.b16 {%0,%1,%2,%3}, [%4];" \
        : "=r"((r)[0]), "=r"((r)[1]), "=r"((r)[2]), "=r"((r)[3]) : "r"(a))

#define MMA16816(d, a, b0, b1) \
    asm volatile("mma.sync.aligned.m16n8k16.row.col.f32.f16.f16.f32 " \
        "{%0,%1,%2,%3}, {%4,%5,%6,%7}, {%8,%9}, {%0,%1,%2,%3};" \
        : "+f"((d)[0]), "+f"((d)[1]), "+f"((d)[2]), "+f"((d)[3]) \
        : "r"((a)[0]), "r"((a)[1]), "r"((a)[2]), "r"((a)[3]), "r"(b0), "r"(b1))

// smem tile layout: [rows][BK] halves, 64B rows = 4 x 16B chunks.
// Swizzle: chunk c' = c ^ ((row>>1)&3) -> conflict-free for cp.async stores
// and ldmatrix reads (verified R14/R15).
__device__ __forceinline__ uint32_t sw_off(int row, int c) {
    return (uint32_t)(row * 64 + ((c ^ ((row >> 1) & 3)) << 4));
}

// ---------------------------------------------------------------------------
// Kernel 1: MXFP4 activation quantization -> fp16
// ---------------------------------------------------------------------------
struct __align__(8) H4 { __half v[4]; };

__device__ __forceinline__ float snap_grid(float a) {
    // nearest on {0,.5,1,1.5,2,3,4,6}; ties go LOW (matches searchsorted-left ref)
    return a > 5.0f  ? 6.0f :
           a > 3.5f  ? 4.0f :
           a > 2.5f  ? 3.0f :
           a > 1.75f ? 2.0f :
           a > 1.25f ? 1.5f :
           a > 0.75f ? 1.0f :
           a > 0.25f ? 0.5f : 0.0f;
}

__global__ void __launch_bounds__(256) quant_x_kernel(const float* __restrict__ x) {
    size_t idx = (size_t)blockIdx.x * 256 + threadIdx.x;       // float4 index
    float4 v = reinterpret_cast<const float4*>(x)[idx];

    // 32-elem block amax: 8 consecutive lanes (float4-aligned to blocks)
    float am = fmaxf(fmaxf(fabsf(v.x), fabsf(v.y)), fmaxf(fabsf(v.z), fabsf(v.w)));
    am = fmaxf(am, __shfl_xor_sync(0xffffffffu, am, 1));
    am = fmaxf(am, __shfl_xor_sync(0xffffffffu, am, 2));
    am = fmaxf(am, __shfl_xor_sync(0xffffffffu, am, 4));
    am = fmaxf(am, 1e-12f);

    float scale = __half2float(__float2half_rn(__fdiv_rn(am, 6.0f)));  // fp16 round-trip
    float denom = fmaxf(scale, 1e-12f);

    float e[4] = {v.x, v.y, v.z, v.w};
    H4 hi;
#pragma unroll
    for (int i = 0; i < 4; i++) {
        float xn = __fdiv_rn(e[i], denom);
        float q  = copysignf(snap_grid(fabsf(xn)), xn) * scale;
        hi.v[i] = __float2half_rn(q);      // rel err <= 2^-12 (q has <=13 sig bits)
    }

    *reinterpret_cast<H4*>(&g_A[idx * 4]) = hi;
}

// ---------------------------------------------------------------------------
// Kernel 2: W -> fp16
// ---------------------------------------------------------------------------
__global__ void __launch_bounds__(256) quant_w_kernel(const float* __restrict__ W) {
    size_t idx = (size_t)blockIdx.x * 256 + threadIdx.x;
    float4 v = reinterpret_cast<const float4*>(W)[idx];
    H4 h;
    h.v[0] = __float2half_rn(v.x);
    h.v[1] = __float2half_rn(v.y);
    h.v[2] = __float2half_rn(v.z);
    h.v[3] = __float2half_rn(v.w);
    *reinterpret_cast<H4*>(&g_B[idx * 4]) = h;
}

// ---------------------------------------------------------------------------
// Kernel 3: multistage mma.sync GEMM, CTA 128x256, warp 64x64, K = 4096
// ---------------------------------------------------------------------------
__device__ __forceinline__ void load_stage(uint32_t sb, int stg, int kk,
                                           int m0, int n0, int tid) {
    const __half* Ap = g_A + (size_t)m0 * K_DIM + kk * BK;
    const __half* Bp = g_B + (size_t)n0 * K_DIM + kk * BK;
    uint32_t as = sb + (uint32_t)stg * STG_BYTES;
    uint32_t bs = as + B_OFF;
#pragma unroll
    for (int i = 0; i < 2; i++) {          // A: 512 chunks of 16B
        int ch = i * 256 + tid;
        int row = ch >> 2, c = ch & 3;
        CP_ASYNC16(as + sw_off(row, c), Ap + (size_t)row * K_DIM + c * 8);
    }
#pragma unroll
    for (int i = 0; i < 4; i++) {          // B: 1024 chunks of 16B
        int ch = i * 256 + tid;
        int row = ch >> 2, c = ch & 3;
        CP_ASYNC16(bs + sw_off(row, c), Bp + (size_t)row * K_DIM + c * 8);
    }
}

__global__ void __launch_bounds__(256, 1) gemm_kernel(const float* __restrict__ bias,
                                                      float* __restrict__ out) {
    extern __shared__ __align__(1024) char smem[];
    uint32_t sb = smem_u32(smem);
    int tid = threadIdx.x;
    int lane = tid & 31, w = tid >> 5;
    int wm = w >> 2, wn = w & 3;           // 2 x 4 warp grid, warp tile 64x64

    // L2-friendly rasterization (GROUP_M supertiles; 64 % 8 == 0 -> all full)
    int pid = blockIdx.x;
    int gsz = GROUP_M * TILES_N;
    int g = pid / gsz;
    int r = pid - g * gsz;
    int m0 = (g * GROUP_M + (r % GROUP_M)) * BM;
    int n0 = (r / GROUP_M) * BN;

    float acc[4][8][4];
#pragma unroll
    for (int a = 0; a < 4; a++)
#pragma unroll
        for (int b = 0; b < 8; b++)
#pragma unroll
            for (int c = 0; c < 4; c++) acc[a][b][c] = 0.0f;

    // prologue: 3 stages in flight
#pragma unroll
    for (int s = 0; s < NSTG - 1; s++) { load_stage(sb, s, s, m0, n0, tid); CP_COMMIT(); }

    // ldmatrix per-lane address precompute (same verified mapping as R15,
    // B replicated for two 32-col groups)
    uint32_t a_row[4]; int a_sw[4];
#pragma unroll
    for (int mb = 0; mb < 4; mb++) {
        int row = wm * 64 + mb * 16 + (lane & 15);
        a_row[mb] = (uint32_t)(row * 64);
        a_sw[mb]  = (row >> 1) & 3;
    }
    int a_chi = lane >> 4;

    uint32_t b_row[4]; int b_sw[4];        // index = grp*2 + p
    int brow_base = (lane & 7) + ((lane >> 4) << 3);
#pragma unroll
    for (int gp = 0; gp < 4; gp++) {
        int grp = gp >> 1, p = gp & 1;
        int row = wn * 64 + grp * 32 + brow_base + p * 16;
        b_row[gp] = (uint32_t)(row * 64);
        b_sw[gp]  = (row >> 1) & 3;
    }
    int b_chi = (lane >> 3) & 1;

    for (int kk = 0; kk < KITERS; kk++) {
        CP_WAIT(2);
        __syncthreads();               // stage kk visible to all warps

        uint32_t as = sb + (uint32_t)(kk & 3) * STG_BYTES;
        uint32_t bs = as + B_OFF;
#pragma unroll
        for (int ks = 0; ks < 2; ks++) {   // BK=32 -> 2 k16 steps
            uint32_t afr[16], bfr[16];
            int ca = 2 * ks + a_chi;
            int cb = 2 * ks + b_chi;
#pragma unroll
            for (int mb = 0; mb < 4; mb++)
                LDSM4(afr + mb * 4, as + a_row[mb] + (uint32_t)((ca ^ a_sw[mb]) << 4));
#pragma unroll
            for (int gp = 0; gp < 4; gp++)
                LDSM4(bfr + gp * 4, bs + b_row[gp] + (uint32_t)((cb ^ b_sw[gp]) << 4));
#pragma unroll
            for (int mb = 0; mb < 4; mb++)
#pragma unroll
                for (int nb = 0; nb < 8; nb++) {
                    int grp = nb >> 2, idx = nb & 3;
                    MMA16816(acc[mb][nb], afr + mb * 4,
                             bfr[grp * 8 + idx * 2], bfr[grp * 8 + idx * 2 + 1]);
                }
        }

        int nk = kk + NSTG - 1;
        if (nk < KITERS) load_stage(sb, nk & 3, nk, m0, n0, tid);
        CP_COMMIT();                   // commit every iter (empty ok) to keep counts aligned
    }

    // epilogue: + bias, float2 stores
    int col0 = n0 + wn * 64 + (lane & 3) * 2;
    float2 bv[8];
#pragma unroll
    for (int nb = 0; nb < 8; nb++) {
        int c = col0 + (nb >> 2) * 32 + (nb & 3) * 8;
        bv[nb].x = __ldg(bias + c);
        bv[nb].y = __ldg(bias + c + 1);
    }
    int rbase = m0 + wm * 64 + (lane >> 2);
#pragma unroll
    for (int mb = 0; mb < 4; mb++) {
        size_t r0 = (size_t)(rbase + mb * 16);
#pragma unroll
        for (int nb = 0; nb < 8; nb++) {
            size_t c = (size_t)(col0 + (nb >> 2) * 32 + (nb & 3) * 8);
            float2 v0 = { acc[mb][nb][0] + bv[nb].x, acc[mb][nb][1] + bv[nb].y };
            float2 v1 = { acc[mb][nb][2] + bv[nb].x, acc[mb][nb][3] + bv[nb].y };
            *reinterpret_cast<float2*>(out + r0 * N_COLS + c)       = v0;
            *reinterpret_cast<float2*>(out + (r0 + 8) * N_COLS + c) = v1;
        }
    }
}

// ---------------------------------------------------------------------------
// Launch
// ---------------------------------------------------------------------------
extern "C" void kernel_launch(void* const* d_in, const int* in_sizes, int n_in,
                              void* d_out, int out_size) {
    const float* x    = (const float*)d_in[0];   // [2,4096,4096]
    const float* W    = (const float*)d_in[1];   // [11008,4096]
    const float* bias = (const float*)d_in[2];   // [11008]
    float* out = (float*)d_out;                  // [2,4096,11008]
    (void)in_sizes; (void)n_in; (void)out_size;

    cudaFuncSetAttribute(gemm_kernel, cudaFuncAttributeMaxDynamicSharedMemorySize, SMEM_TOTAL);

    quant_x_kernel<<<32768, 256>>>(x);           // 33.5M / 4 / 256
    quant_w_kernel<<<44032, 256>>>(W);           // 45.1M / 4 / 256
    gemm_kernel<<<TILES_M * TILES_N, 256, SMEM_TOTAL>>>(bias, out);
}

// round 17
// speedup vs baseline: 1.1791x; 1.1791x over previous
#include <cuda_runtime.h>
#include <cuda_fp16.h>
#include <cstdint>
#include <cstddef>

// ---------------------------------------------------------------------------
// Problem constants
// ---------------------------------------------------------------------------
#define M_ROWS   8192        // 2*4096
#define N_COLS   11008
#define K_DIM    4096
#define KITERS   64          // K = 4096, BK = 64
#define BM       128
#define BN       128
#define BK       64
#define NSTG     3
#define TILES_M  (M_ROWS / BM)      // 64
#define TILES_N  (N_COLS / BN)      // 86
#define GROUP_M  8

#define A_STG    16384              // 128 rows x 128B
#define B_STG    16384
#define STG_BYTES (A_STG + B_STG)   // 32768
#define B_OFF     A_STG
#define SMEM_TOTAL (NSTG * STG_BYTES)   // 98304 (x2 CTAs = 192KB <= 228KB)

// ---------------------------------------------------------------------------
// Device scratch (allocation-free rule: __device__ globals)
// ---------------------------------------------------------------------------
__device__ __align__(256) __half g_A[(size_t)M_ROWS * K_DIM];  // fp16(x_q)
__device__ __align__(256) __half g_B[(size_t)N_COLS * K_DIM];  // fp16(W)

// ---------------------------------------------------------------------------
// Helpers (compute_103-safe vocabulary: cp.async / ldmatrix / mma.sync)
// ---------------------------------------------------------------------------
__device__ __forceinline__ uint32_t smem_u32(const void* p) {
    uint32_t a;
    asm("{ .reg .u64 t; cvta.to.shared.u64 t, %1; cvt.u32.u64 %0, t; }" : "=r"(a) : "l"(p));
    return a;
}

#define CP_ASYNC16(dst, src) \
    asm volatile("cp.async.cg.shared.global [%0], [%1], 16;" :: "r"(dst), "l"(src))
#define CP_COMMIT() asm volatile("cp.async.commit_group;" ::: "memory")
#define CP_WAIT(N)  asm volatile("cp.async.wait_group %0;" :: "n"(N) : "memory")

#define LDSM4(r, a) \
    asm volatile("ldmatrix.sync.aligned.m8n8.x4.shared.b16 {%0,%1,%2,%3}, [%4];" \
        : "=r"((r)[0]), "=r"((r)[1]), "=r"((r)[2]), "=r"((r)[3]) : "r"(a))

#define MMA16816(d, a, b0, b1) \
    asm volatile("mma.sync.aligned.m16n8k16.row.col.f32.f16.f16.f32 " \
        "{%0,%1,%2,%3}, {%4,%5,%6,%7}, {%8,%9}, {%0,%1,%2,%3};" \
        : "+f"((d)[0]), "+f"((d)[1]), "+f"((d)[2]), "+f"((d)[3]) \
        : "r"((a)[0]), "r"((a)[1]), "r"((a)[2]), "r"((a)[3]), "r"(b0), "r"(b1))

// smem tile layout: [rows][BK] halves, 128B rows = 8 x 16B chunks.
// Swizzle: chunk c' = c ^ (row & 7) -> conflict-free for cp.async stores
// (8 lanes per row cover 8 distinct chunk-banks) and every ldmatrix phase
// (8 consecutive rows at fixed c hit 8 distinct chunk-banks).
__device__ __forceinline__ uint32_t sw_off(int row, int c) {
    return (uint32_t)(row * 128 + ((c ^ (row & 7)) << 4));
}

// ---------------------------------------------------------------------------
// Kernel 1: MXFP4 activation quantization -> fp16
// ---------------------------------------------------------------------------
struct __align__(8) H4 { __half v[4]; };

__device__ __forceinline__ float snap_grid(float a) {
    // nearest on {0,.5,1,1.5,2,3,4,6}; ties go LOW (matches searchsorted-left ref)
    return a > 5.0f  ? 6.0f :
           a > 3.5f  ? 4.0f :
           a > 2.5f  ? 3.0f :
           a > 1.75f ? 2.0f :
           a > 1.25f ? 1.5f :
           a > 0.75f ? 1.0f :
           a > 0.25f ? 0.5f : 0.0f;
}

__global__ void __launch_bounds__(256) quant_x_kernel(const float* __restrict__ x) {
    size_t idx = (size_t)blockIdx.x * 256 + threadIdx.x;       // float4 index
    float4 v = reinterpret_cast<const float4*>(x)[idx];

    // 32-elem block amax: 8 consecutive lanes (float4-aligned to blocks)
    float am = fmaxf(fmaxf(fabsf(v.x), fabsf(v.y)), fmaxf(fabsf(v.z), fabsf(v.w)));
    am = fmaxf(am, __shfl_xor_sync(0xffffffffu, am, 1));
    am = fmaxf(am, __shfl_xor_sync(0xffffffffu, am, 2));
    am = fmaxf(am, __shfl_xor_sync(0xffffffffu, am, 4));
    am = fmaxf(am, 1e-12f);

    float scale = __half2float(__float2half_rn(__fdiv_rn(am, 6.0f)));  // fp16 round-trip
    float denom = fmaxf(scale, 1e-12f);

    float e[4] = {v.x, v.y, v.z, v.w};
    H4 hi;
#pragma unroll
    for (int i = 0; i < 4; i++) {
        float xn = __fdiv_rn(e[i], denom);
        float q  = copysignf(snap_grid(fabsf(xn)), xn) * scale;
        hi.v[i] = __float2half_rn(q);      // rel err <= 2^-12 (q has <=13 sig bits)
    }

    *reinterpret_cast<H4*>(&g_A[idx * 4]) = hi;
}

// ---------------------------------------------------------------------------
// Kernel 2: W -> fp16
// ---------------------------------------------------------------------------
__global__ void __launch_bounds__(256) quant_w_kernel(const float* __restrict__ W) {
    size_t idx = (size_t)blockIdx.x * 256 + threadIdx.x;
    float4 v = reinterpret_cast<const float4*>(W)[idx];
    H4 h;
    h.v[0] = __float2half_rn(v.x);
    h.v[1] = __float2half_rn(v.y);
    h.v[2] = __float2half_rn(v.z);
    h.v[3] = __float2half_rn(v.w);
    *reinterpret_cast<H4*>(&g_B[idx * 4]) = h;
}

// ---------------------------------------------------------------------------
// Kernel 3: multistage mma.sync GEMM, CTA 128x128, warp 64x32, BK = 64
// ---------------------------------------------------------------------------
__device__ __forceinline__ void load_stage(uint32_t sb, int stg, int kk,
                                           int m0, int n0, int tid) {
    const __half* Ap = g_A + (size_t)m0 * K_DIM + kk * BK;
    const __half* Bp = g_B + (size_t)n0 * K_DIM + kk * BK;
    uint32_t as = sb + (uint32_t)stg * STG_BYTES;
    uint32_t bs = as + B_OFF;
#pragma unroll
    for (int i = 0; i < 4; i++) {          // A: 1024 chunks of 16B
        int ch = i * 256 + tid;
        int row = ch >> 3, c = ch & 7;
        uint32_t off = sw_off(row, c);
        CP_ASYNC16(as + off, Ap + (size_t)row * K_DIM + c * 8);
        CP_ASYNC16(bs + off, Bp + (size_t)row * K_DIM + c * 8);
    }
}

__global__ void __launch_bounds__(256, 2) gemm_kernel(const float* __restrict__ bias,
                                                      float* __restrict__ out) {
    extern __shared__ __align__(1024) char smem[];
    uint32_t sb = smem_u32(smem);
    int tid = threadIdx.x;
    int lane = tid & 31, w = tid >> 5;
    int wm = w >> 2, wn = w & 3;           // 2 x 4 warp grid, warp tile 64x32

    // L2-friendly rasterization (GROUP_M supertiles; 64 % 8 == 0 -> all full)
    int pid = blockIdx.x;
    int gsz = GROUP_M * TILES_N;
    int g = pid / gsz;
    int r = pid - g * gsz;
    int m0 = (g * GROUP_M + (r % GROUP_M)) * BM;
    int n0 = (r / GROUP_M) * BN;

    float acc[4][4][4];
#pragma unroll
    for (int a = 0; a < 4; a++)
#pragma unroll
        for (int b = 0; b < 4; b++)
#pragma unroll
            for (int c = 0; c < 4; c++) acc[a][b][c] = 0.0f;

    // prologue: 2 stages in flight
#pragma unroll
    for (int s = 0; s < NSTG - 1; s++) { load_stage(sb, s, s, m0, n0, tid); CP_COMMIT(); }

    // ldmatrix per-lane address precompute (same verified fragment mapping as R15)
    uint32_t a_row[4]; int a_sw[4];
#pragma unroll
    for (int mb = 0; mb < 4; mb++) {
        int row = wm * 64 + mb * 16 + (lane & 15);
        a_row[mb] = (uint32_t)(row * 128);
        a_sw[mb]  = row & 7;
    }
    int a_chi = lane >> 4;
    uint32_t b_row[2]; int b_sw[2];
    int brow0 = wn * 32 + (lane & 7) + ((lane >> 4) << 3);
#pragma unroll
    for (int p = 0; p < 2; p++) {
        int row = brow0 + p * 16;
        b_row[p] = (uint32_t)(row * 128);
        b_sw[p]  = row & 7;
    }
    int b_chi = (lane >> 3) & 1;

    for (int kk = 0; kk < KITERS; kk++) {
        CP_WAIT(1);
        __syncthreads();               // stage kk visible to all warps

        uint32_t as = sb + (uint32_t)(kk % NSTG) * STG_BYTES;
        uint32_t bs = as + B_OFF;
#pragma unroll
        for (int ks = 0; ks < 4; ks++) {   // BK=64 -> 4 k16 steps
            uint32_t afr[16], bfr[8];
            int ca = 2 * ks + a_chi;
            int cb = 2 * ks + b_chi;
#pragma unroll
            for (int mb = 0; mb < 4; mb++)
                LDSM4(afr + mb * 4, as + a_row[mb] + (uint32_t)((ca ^ a_sw[mb]) << 4));
#pragma unroll
            for (int p = 0; p < 2; p++)
                LDSM4(bfr + p * 4, bs + b_row[p] + (uint32_t)((cb ^ b_sw[p]) << 4));
#pragma unroll
            for (int mb = 0; mb < 4; mb++)
#pragma unroll
                for (int nb = 0; nb < 4; nb++)
                    MMA16816(acc[mb][nb], afr + mb * 4, bfr[nb * 2], bfr[nb * 2 + 1]);
        }

        int nk = kk + NSTG - 1;
        if (nk < KITERS) load_stage(sb, nk % NSTG, nk, m0, n0, tid);
        CP_COMMIT();                   // commit every iter (empty ok) to keep counts aligned
    }

    // epilogue: + bias, float2 stores
    int col0 = n0 + wn * 32 + (lane & 3) * 2;
    float2 bv[4];
#pragma unroll
    for (int nb = 0; nb < 4; nb++) {
        bv[nb].x = __ldg(bias + col0 + nb * 8);
        bv[nb].y = __ldg(bias + col0 + nb * 8 + 1);
    }
    int rbase = m0 + wm * 64 + (lane >> 2);
#pragma unroll
    for (int mb = 0; mb < 4; mb++) {
        size_t r0 = (size_t)(rbase + mb * 16);
#pragma unroll
        for (int nb = 0; nb < 4; nb++) {
            size_t c = (size_t)(col0 + nb * 8);
            float2 v0 = { acc[mb][nb][0] + bv[nb].x, acc[mb][nb][1] + bv[nb].y };
            float2 v1 = { acc[mb][nb][2] + bv[nb].x, acc[mb][nb][3] + bv[nb].y };
            *reinterpret_cast<float2*>(out + r0 * N_COLS + c)       = v0;
            *reinterpret_cast<float2*>(out + (r0 + 8) * N_COLS + c) = v1;
        }
    }
}

// ---------------------------------------------------------------------------
// Launch
// ---------------------------------------------------------------------------
extern "C" void kernel_launch(void* const* d_in, const int* in_sizes, int n_in,
                              void* d_out, int out_size) {
    const float* x    = (const float*)d_in[0];   // [2,4096,4096]
    const float* W    = (const float*)d_in[1];   // [11008,4096]
    const float* bias = (const float*)d_in[2];   // [11008]
    float* out = (float*)d_out;                  // [2,4096,11008]
    (void)in_sizes; (void)n_in; (void)out_size;

    cudaFuncSetAttribute(gemm_kernel, cudaFuncAttributeMaxDynamicSharedMemorySize, SMEM_TOTAL);

    quant_x_kernel<<<32768, 256>>>(x);           // 33.5M / 4 / 256
    quant_w_kernel<<<44032, 256>>>(W);           // 45.1M / 4 / 256
    gemm_kernel<<<TILES_M * TILES_N, 256, SMEM_TOTAL>>>(bias, out);
}